// round 13
// baseline (speedup 1.0000x reference)
#include <cuda_runtime.h>
#include <cstdint>
#include <cstddef>

#define SROWS 66  // 2 + HEAD_SIZE

// scratch
__device__ float g_act[8192 * 160];                 // tanh acts, PRE-ROUNDED to tf32
__device__ __align__(16) float g_w1cv[2048 * 160];  // W1 pre-rounded to tf32, [K,160]

__device__ __forceinline__ uint32_t f2tf32(float f) {
    uint32_t u;
    asm("cvt.rna.tf32.f32 %0, %1;" : "=r"(u) : "f"(f));
    return u;
}

#define MMA_TF32(acc, a0, a1, a2, a3, b0, b1)                                 \
    asm volatile(                                                             \
        "mma.sync.aligned.m16n8k8.row.col.f32.tf32.tf32.f32 "                 \
        "{%0,%1,%2,%3}, {%4,%5,%6,%7}, {%8,%9}, {%0,%1,%2,%3};"               \
        : "+f"((acc)[0]), "+f"((acc)[1]), "+f"((acc)[2]), "+f"((acc)[3])      \
        : "r"(a0), "r"(a1), "r"(a2), "r"(a3), "r"(b0), "r"(b1))

// ---------------------------------------------------------------------------
// Kernel T: round W1 to tf32 (keeps [K,160] layout == .col B-fragment layout)
// ---------------------------------------------------------------------------
__global__ void k_w1cv(const float* __restrict__ w1, int n)
{
    int idx = blockIdx.x * blockDim.x + threadIdx.x;
    if (idx >= n) return;
    g_w1cv[idx] = __uint_as_float(f2tf32(w1[idx]));
}

// ---------------------------------------------------------------------------
// Kernel A (mma.sync tf32, 2-stage pipelined):
//   act[M,160] = tanh( XM[M,2048] @ W1[2048,160] )
// 512 thr, tile M=64 x N=160, warp grid 4m x 4n, warp tile m16 x n40.
// K chunks of 32; LDGs for chunk kt+1 issued before MMAs on chunk kt.
// Dynamic smem: 2 stages x (As 64x36 + Bs 32x168) words = 61440 B.
// ---------------------------------------------------------------------------
#define G1_AW (64 * 36)
#define G1_BW (32 * 168)
#define G1_SMEM ((G1_AW + G1_BW) * 2 * 4)

__global__ __launch_bounds__(512) void k_gemm1_mma(
    const float* __restrict__ x, const float* __restrict__ state,
    const float* __restrict__ tmx, const int* __restrict__ ip,
    int B, int S, int D)
{
    extern __shared__ uint32_t smw[];
    uint32_t* Asb[2] = { smw, smw + G1_AW };
    uint32_t* Bsb[2] = { smw + 2 * G1_AW, smw + 2 * G1_AW + G1_BW };

    const int tid = threadIdx.x;
    const int wid = tid >> 5, lane = tid & 31;
    const int g = lane >> 2, t = lane & 3;
    const int warp_m = wid & 3, warp_n = wid >> 2;
    const int mbase = blockIdx.x * 64;
    const int i1 = SROWS * ip[0] + 1;

    // A loader: 512 float4 slots, exactly 1 per thread
    const int cg = tid & 7;
    const int r = tid >> 3;
    const float* xrow;
    const float* prow;
    {
        int m = mbase + r;
        int b = m / S;
        int s = m - b * S;
        xrow = x + (size_t)m * D + cg * 4;
        prow = (s == 0) ? (state + ((size_t)b * SROWS + i1) * D + cg * 4)
                        : (x + (size_t)(m - 1) * D + cg * 4);
    }
    const int a_off = r * 36 + cg * 4;
    // B loader: 1280 float4 slots; slots tid, tid+512, tid+1024 (tid<256)
    int brow[3], bcol[3];
#pragma unroll
    for (int it = 0; it < 3; it++) {
        int slot = tid + it * 512;
        if (slot < 1280) {
            brow[it] = slot / 40;
            bcol[it] = (slot - brow[it] * 40) * 4;
        } else { brow[it] = -1; bcol[it] = 0; }
    }

    float acc[5][4];
#pragma unroll
    for (int nt = 0; nt < 5; nt++)
#pragma unroll
        for (int j = 0; j < 4; j++) acc[nt][j] = 0.f;

    const int KT = D >> 5;  // 64 chunks of 32

    // ---- prologue: load + fill stage 0 ----
    {
        float4 xv = *(const float4*)(xrow);
        float4 pv = *(const float4*)(prow);
        float4 tv = *(const float4*)(tmx + cg * 4);
        uint4 o;
        o.x = f2tf32(fmaf(pv.x - xv.x, tv.x, xv.x));
        o.y = f2tf32(fmaf(pv.y - xv.y, tv.y, xv.y));
        o.z = f2tf32(fmaf(pv.z - xv.z, tv.z, xv.z));
        o.w = f2tf32(fmaf(pv.w - xv.w, tv.w, xv.w));
        *(uint4*)(Asb[0] + a_off) = o;
#pragma unroll
        for (int it = 0; it < 3; it++)
            if (brow[it] >= 0)
                *(uint4*)(Bsb[0] + brow[it] * 168 + bcol[it]) =
                    *(const uint4*)(g_w1cv + (size_t)brow[it] * 160 + bcol[it]);
    }
    __syncthreads();

    for (int kt = 0; kt < KT; kt++) {
        const int cur = kt & 1;
        const bool more = (kt + 1) < KT;

        // ---- issue raw LDGs for chunk kt+1 (no arithmetic yet) ----
        float4 xv_n, pv_n, tv_n;
        uint4 b_n[3];
        if (more) {
            const int kn = (kt + 1) << 5;
            xv_n = *(const float4*)(xrow + kn);
            pv_n = *(const float4*)(prow + kn);
            tv_n = *(const float4*)(tmx + kn + cg * 4);
            const float* wsrc = g_w1cv + (size_t)kn * 160;
#pragma unroll
            for (int it = 0; it < 3; it++)
                if (brow[it] >= 0)
                    b_n[it] = *(const uint4*)(wsrc + (size_t)brow[it] * 160 + bcol[it]);
        }

        // ---- MMAs on stage cur (overlaps the LDGs above) ----
        const uint32_t* As = Asb[cur];
        const uint32_t* Bs = Bsb[cur];
#pragma unroll
        for (int ks = 0; ks < 4; ks++) {
            const int k0 = ks * 8;
            const int ar = warp_m * 16 + g;
            uint32_t a0 = As[ar * 36 + k0 + t];
            uint32_t a1 = As[(ar + 8) * 36 + k0 + t];
            uint32_t a2 = As[ar * 36 + k0 + t + 4];
            uint32_t a3 = As[(ar + 8) * 36 + k0 + t + 4];
#pragma unroll
            for (int nt = 0; nt < 5; nt++) {
                const int nc = warp_n * 40 + nt * 8 + g;
                uint32_t b0 = Bs[(k0 + t) * 168 + nc];
                uint32_t b1 = Bs[(k0 + t + 4) * 168 + nc];
                MMA_TF32(acc[nt], a0, a1, a2, a3, b0, b1);
            }
        }
        __syncthreads();

        // ---- finish chunk kt+1: arithmetic + store to other stage ----
        if (more) {
            const int nxt = cur ^ 1;
            uint4 o;
            o.x = f2tf32(fmaf(pv_n.x - xv_n.x, tv_n.x, xv_n.x));
            o.y = f2tf32(fmaf(pv_n.y - xv_n.y, tv_n.y, xv_n.y));
            o.z = f2tf32(fmaf(pv_n.z - xv_n.z, tv_n.z, xv_n.z));
            o.w = f2tf32(fmaf(pv_n.w - xv_n.w, tv_n.w, xv_n.w));
            *(uint4*)(Asb[nxt] + a_off) = o;
#pragma unroll
            for (int it = 0; it < 3; it++)
                if (brow[it] >= 0)
                    *(uint4*)(Bsb[nxt] + brow[it] * 168 + bcol[it]) = b_n[it];
            __syncthreads();
        }
    }

    // ---- epilogue: tanh, round to tf32 (GEMM2's A operand), store ----
    const int m0 = mbase + warp_m * 16 + g;
#pragma unroll
    for (int nt = 0; nt < 5; nt++) {
        const int n = warp_n * 40 + nt * 8 + t * 2;
        float2 lo, hi;
        lo.x = __uint_as_float(f2tf32(tanhf(acc[nt][0])));
        lo.y = __uint_as_float(f2tf32(tanhf(acc[nt][1])));
        hi.x = __uint_as_float(f2tf32(tanhf(acc[nt][2])));
        hi.y = __uint_as_float(f2tf32(tanhf(acc[nt][3])));
        *(float2*)(g_act + (size_t)m0 * 160 + n) = lo;
        *(float2*)(g_act + (size_t)(m0 + 8) * 160 + n) = hi;
    }
}

// ---------------------------------------------------------------------------
// Kernel B (mma.sync tf32): GEMM2 + epilogue, 5 f per block.
// Tile: 64 tokens x 128 d. 256 thr, warp grid 2m x 4n, warp tile m32 x n32.
// Single-pass 64-row Cs transpose; 2 barriers per f.
// Dynamic smem: As 64x36 + Bs 32x136 + Cs 64x132 words = 60416 B.
// ---------------------------------------------------------------------------
#define G2_AW (64 * 36)
#define G2_BW (32 * 136)
#define G2_CW (64 * 132)
#define G2_SMEM ((G2_AW + G2_BW + G2_CW) * 4)

__global__ __launch_bounds__(256) void k_gemm2_mma(
    const float* __restrict__ x, const float* __restrict__ state,
    const float* __restrict__ w2,
    const float* __restrict__ mk, const float* __restrict__ mw,
    const float* __restrict__ mv, const float* __restrict__ mr,
    const float* __restrict__ mg,
    const int* __restrict__ ip,
    float* __restrict__ out, int B, int S, int D)
{
    extern __shared__ uint32_t smw[];
    uint32_t* As = smw;
    uint32_t* Bs = smw + G2_AW;
    float*    Cs = (float*)(smw + G2_AW + G2_BW);

    const int tid = threadIdx.x;
    const int wid = tid >> 5, lane = tid & 31;
    const int g = lane >> 2, t = lane & 3;
    const int warp_m = wid & 1, warp_n = wid >> 1;
    const int dbase = blockIdx.x * 128;
    const int mbase = blockIdx.y * 64;
    const int i1 = SROWS * ip[0] + 1;

    // B fill: 1024 float4 slots, 4/thread
    int br[4], bc[4];
#pragma unroll
    for (int it = 0; it < 4; it++) {
        int slot = tid + it * 256;
        br[it] = slot >> 5;
        bc[it] = (slot & 31) * 4;
    }
    // A fill: 512 float4 slots, 2/thread
    int arr[2], acg[2];
#pragma unroll
    for (int it = 0; it < 2; it++) {
        int slot = tid + it * 256;
        arr[it] = slot >> 3;
        acg[it] = (slot & 7) * 4;
    }

    for (int f = 0; f < 5; f++) {
        // ---- stage As (g_act already tf32) + Bs (tf32 round) ----
        // safe vs. previous f: epilogue reads only Cs/gmem, and the barrier
        // below separates these writes from this f's fragment reads.
#pragma unroll
        for (int it = 0; it < 2; it++)
            *(uint4*)(As + arr[it] * 36 + acg[it]) =
                *(const uint4*)(g_act + (size_t)(mbase + arr[it]) * 160 + f * 32 + acg[it]);
#pragma unroll
        for (int it = 0; it < 4; it++) {
            float4 w = *(const float4*)(w2 + ((size_t)f * 32 + br[it]) * D + dbase + bc[it]);
            uint4 o;
            o.x = f2tf32(w.x); o.y = f2tf32(w.y);
            o.z = f2tf32(w.z); o.w = f2tf32(w.w);
            *(uint4*)(Bs + br[it] * 136 + bc[it]) = o;
        }
        __syncthreads();   // staging done; also guards Cs reuse (prev epilogue done)

        float acc[2][4][4];
#pragma unroll
        for (int mi = 0; mi < 2; mi++)
#pragma unroll
            for (int nt = 0; nt < 4; nt++)
#pragma unroll
                for (int j = 0; j < 4; j++) acc[mi][nt][j] = 0.f;

#pragma unroll
        for (int ks = 0; ks < 4; ks++) {
            const int k0 = ks * 8;
            uint32_t a[2][4];
#pragma unroll
            for (int mi = 0; mi < 2; mi++) {
                const int ar = warp_m * 32 + mi * 16 + g;
                a[mi][0] = As[ar * 36 + k0 + t];
                a[mi][1] = As[(ar + 8) * 36 + k0 + t];
                a[mi][2] = As[ar * 36 + k0 + t + 4];
                a[mi][3] = As[(ar + 8) * 36 + k0 + t + 4];
            }
#pragma unroll
            for (int nt = 0; nt < 4; nt++) {
                const int nc = warp_n * 32 + nt * 8 + g;
                uint32_t b0 = Bs[(k0 + t) * 136 + nc];
                uint32_t b1 = Bs[(k0 + t + 4) * 136 + nc];
#pragma unroll
                for (int mi = 0; mi < 2; mi++)
                    MMA_TF32(acc[mi][nt], a[mi][0], a[mi][1], a[mi][2], a[mi][3], b0, b1);
            }
        }

        // ---- single-pass transpose: every warp writes its disjoint Cs region ----
#pragma unroll
        for (int mi = 0; mi < 2; mi++)
#pragma unroll
            for (int h = 0; h < 2; h++) {
                const int row = warp_m * 32 + mi * 16 + h * 8 + g;
#pragma unroll
                for (int nt = 0; nt < 4; nt++) {
                    const int c = warp_n * 32 + nt * 8 + t * 2;
                    *(float2*)(Cs + row * 132 + c) =
                        make_float2(acc[mi][nt][h * 2 + 0], acc[mi][nt][h * 2 + 1]);
                }
            }
        __syncthreads();

        // ---- coalesced epilogue over all 64 rows: 8 float4 slots/thread ----
        const float* st = (f == 0) ? mk : (f == 1) ? mw : (f == 2) ? mv
                        : (f == 3) ? mr : mg;
#pragma unroll
        for (int it = 0; it < 8; it++) {
            int slot = tid + it * 256;
            int row = slot >> 5;
            int c = (slot & 31) * 4;
            int m = mbase + row;
            int b = m / S;
            int s = m - b * S;
            const int d = dbase + c;
            float4 cv = *(const float4*)(Cs + row * 132 + c);
            float4 xv = *(const float4*)(x + (size_t)m * D + d);
            float4 pv = (s == 0)
                ? *(const float4*)(state + ((size_t)b * SROWS + i1) * D + d)
                : *(const float4*)(x + (size_t)(m - 1) * D + d);
            float4 stv = *(const float4*)(st + d);
            float4 o;
            o.x = fmaf(pv.x - xv.x, stv.x + cv.x, xv.x);
            o.y = fmaf(pv.y - xv.y, stv.y + cv.y, xv.y);
            o.z = fmaf(pv.z - xv.z, stv.z + cv.z, xv.z);
            o.w = fmaf(pv.w - xv.w, stv.w + cv.w, xv.w);
            *(float4*)(out + ((size_t)m * 5 + f) * D + d) = o;
        }
    }
}

// ---------------------------------------------------------------------------
// Kernel C: new_state = state with row i1 <- x[:, S-1, :]
// ---------------------------------------------------------------------------
__global__ void k_state(
    const float* __restrict__ x, const float* __restrict__ state,
    const int* __restrict__ ip, float* __restrict__ outs,
    int B, int S, int D)
{
    int idx = blockIdx.x * blockDim.x + threadIdx.x;
    int n = B * SROWS * D;
    if (idx >= n) return;
    int i1 = SROWS * ip[0] + 1;
    int d = idx % D;
    int r = (idx / D) % SROWS;
    int b = idx / (D * SROWS);
    float v = (r == i1) ? x[((size_t)b * S + (S - 1)) * D + d] : state[idx];
    outs[idx] = v;
}

extern "C" void kernel_launch(void* const* d_in, const int* in_sizes, int n_in,
                              void* d_out, int out_size)
{
    const float* x     = (const float*)d_in[0];
    const float* state = (const float*)d_in[1];
    const float* tmx   = (const float*)d_in[2];
    const float* w1    = (const float*)d_in[3];
    const float* w2    = (const float*)d_in[4];
    const float* mk    = (const float*)d_in[5];
    const float* mw    = (const float*)d_in[6];
    const float* mv    = (const float*)d_in[7];
    const float* mr    = (const float*)d_in[8];
    const float* mg    = (const float*)d_in[9];
    const int*   ip    = (const int*)d_in[10];

    const int D = in_sizes[2];
    const int B = in_sizes[1] / (SROWS * D);
    const int S = in_sizes[0] / (B * D);
    const int M = B * S;

    float* out  = (float*)d_out;
    float* outs = out + (size_t)M * 5 * D;

    cudaFuncSetAttribute(k_gemm1_mma,
                         cudaFuncAttributeMaxDynamicSharedMemorySize, G1_SMEM);
    cudaFuncSetAttribute(k_gemm2_mma,
                         cudaFuncAttributeMaxDynamicSharedMemorySize, G2_SMEM);

    k_w1cv<<<(160 * D + 255) / 256, 256>>>(w1, 160 * D);
    k_gemm1_mma<<<M / 64, 512, G1_SMEM>>>(x, state, tmx, ip, B, S, D);

    dim3 g2(D / 128, M / 64);
    k_gemm2_mma<<<g2, 256, G2_SMEM>>>(x, state, w2, mk, mw, mv, mr, mg, ip, out, B, S, D);

    size_t main_elems  = (size_t)M * 5 * D;
    size_t state_elems = (size_t)B * SROWS * D;
    if ((size_t)out_size >= main_elems + state_elems) {
        int n = B * SROWS * D;
        k_state<<<(n + 255) / 256, 256>>>(x, state, ip, outs, B, S, D);
    }
}

// round 14
// speedup vs baseline: 1.2097x; 1.2097x over previous
#include <cuda_runtime.h>
#include <cstdint>
#include <cstddef>

#define SROWS 66  // 2 + HEAD_SIZE

// scratch
__device__ float g_act[8192 * 160];                 // tanh acts, PRE-ROUNDED to tf32
__device__ __align__(16) float g_w1cv[2048 * 160];  // W1 pre-rounded to tf32, [K,160]

__device__ __forceinline__ uint32_t f2tf32(float f) {
    uint32_t u;
    asm("cvt.rna.tf32.f32 %0, %1;" : "=r"(u) : "f"(f));
    return u;
}

#define MMA_TF32(acc, a0, a1, a2, a3, b0, b1)                                 \
    asm volatile(                                                             \
        "mma.sync.aligned.m16n8k8.row.col.f32.tf32.tf32.f32 "                 \
        "{%0,%1,%2,%3}, {%4,%5,%6,%7}, {%8,%9}, {%0,%1,%2,%3};"               \
        : "+f"((acc)[0]), "+f"((acc)[1]), "+f"((acc)[2]), "+f"((acc)[3])      \
        : "r"(a0), "r"(a1), "r"(a2), "r"(a3), "r"(b0), "r"(b1))

// ---------------------------------------------------------------------------
// Kernel T: round W1 to tf32 (keeps [K,160] layout == .col B-fragment layout)
// ---------------------------------------------------------------------------
__global__ void k_w1cv(const float* __restrict__ w1, int n)
{
    int idx = blockIdx.x * blockDim.x + threadIdx.x;
    if (idx >= n) return;
    g_w1cv[idx] = __uint_as_float(f2tf32(w1[idx]));
}

// ---------------------------------------------------------------------------
// Kernel A (mma.sync tf32): act[M,160] = tanh( XM[M,2048] @ W1[2048,160] )
// 256 thr (8 warps), tile M=32 x N=160 -> grid 256 (~2 blocks/SM for
// cross-block latency hiding). Warp grid 2m x 4n, warp tile m16 x n40.
// K chunks of 32 (4 k-steps). Single-buffered.
// ---------------------------------------------------------------------------
__global__ __launch_bounds__(256) void k_gemm1_mma(
    const float* __restrict__ x, const float* __restrict__ state,
    const float* __restrict__ tmx, const int* __restrict__ ip,
    int B, int S, int D)
{
    __shared__ uint32_t As[32 * 36];    // [m][k], stride 36 -> conflict-free frags
    __shared__ uint32_t Bs[32 * 168];   // [k][n], stride 168 -> conflict-free frags

    const int tid = threadIdx.x;
    const int wid = tid >> 5, lane = tid & 31;
    const int g = lane >> 2, t = lane & 3;
    const int warp_m = wid & 1, warp_n = wid >> 1;
    const int mbase = blockIdx.x * 32;
    const int i1 = SROWS * ip[0] + 1;

    // A loader: 32 rows x 8 float4 slots = 256 slots, exactly 1 per thread
    const int cg = tid & 7;
    const int r = tid >> 3;
    const float* xrow;
    const float* prow;
    uint32_t* adst;
    {
        int m = mbase + r;
        int b = m / S;
        int s = m - b * S;
        xrow = x + (size_t)m * D + cg * 4;
        prow = (s == 0) ? (state + ((size_t)b * SROWS + i1) * D + cg * 4)
                        : (x + (size_t)(m - 1) * D + cg * 4);
        adst = As + r * 36 + cg * 4;
    }
    // B loader: 1280 float4 slots, 5 per thread
    int brow[5], bcol[5];
#pragma unroll
    for (int it = 0; it < 5; it++) {
        int slot = tid + it * 256;
        brow[it] = slot / 40;
        bcol[it] = (slot - brow[it] * 40) * 4;
    }

    float acc[5][4];
#pragma unroll
    for (int nt = 0; nt < 5; nt++)
#pragma unroll
        for (int j = 0; j < 4; j++) acc[nt][j] = 0.f;

    const int KT = D >> 5;  // 64 chunks of 32
    for (int kt = 0; kt < KT; kt++) {
        const int kbase = kt << 5;
        // ---- fill A: mixing + tf32 round ----
        {
            float4 xv = *(const float4*)(xrow + kbase);
            float4 pv = *(const float4*)(prow + kbase);
            float4 tv = *(const float4*)(tmx + kbase + cg * 4);
            uint4 o;
            o.x = f2tf32(fmaf(pv.x - xv.x, tv.x, xv.x));
            o.y = f2tf32(fmaf(pv.y - xv.y, tv.y, xv.y));
            o.z = f2tf32(fmaf(pv.z - xv.z, tv.z, xv.z));
            o.w = f2tf32(fmaf(pv.w - xv.w, tv.w, xv.w));
            *(uint4*)(adst) = o;
        }
        // ---- fill B: copy pre-rounded W1 rows (L2-resident) ----
        {
            const float* wsrc = g_w1cv + (size_t)kbase * 160;
#pragma unroll
            for (int it = 0; it < 5; it++)
                *(uint4*)(Bs + brow[it] * 168 + bcol[it]) =
                    *(const uint4*)(wsrc + (size_t)brow[it] * 160 + bcol[it]);
        }
        __syncthreads();

#pragma unroll
        for (int ks = 0; ks < 4; ks++) {
            const int k0 = ks * 8;
            const int ar = warp_m * 16 + g;
            uint32_t a0 = As[ar * 36 + k0 + t];
            uint32_t a1 = As[(ar + 8) * 36 + k0 + t];
            uint32_t a2 = As[ar * 36 + k0 + t + 4];
            uint32_t a3 = As[(ar + 8) * 36 + k0 + t + 4];
#pragma unroll
            for (int nt = 0; nt < 5; nt++) {
                const int nc = warp_n * 40 + nt * 8 + g;
                uint32_t b0 = Bs[(k0 + t) * 168 + nc];
                uint32_t b1 = Bs[(k0 + t + 4) * 168 + nc];
                MMA_TF32(acc[nt], a0, a1, a2, a3, b0, b1);
            }
        }
        __syncthreads();
    }

    // ---- epilogue: tanh, round to tf32 (GEMM2's A operand), store ----
    const int m0 = mbase + warp_m * 16 + g;
#pragma unroll
    for (int nt = 0; nt < 5; nt++) {
        const int n = warp_n * 40 + nt * 8 + t * 2;
        float2 lo, hi;
        lo.x = __uint_as_float(f2tf32(tanhf(acc[nt][0])));
        lo.y = __uint_as_float(f2tf32(tanhf(acc[nt][1])));
        hi.x = __uint_as_float(f2tf32(tanhf(acc[nt][2])));
        hi.y = __uint_as_float(f2tf32(tanhf(acc[nt][3])));
        *(float2*)(g_act + (size_t)m0 * 160 + n) = lo;
        *(float2*)(g_act + (size_t)(m0 + 8) * 160 + n) = hi;
    }
}

// ---------------------------------------------------------------------------
// Kernel B (mma.sync tf32): GEMM2 + epilogue, 5 f per block.  (R12 proven)
// Tile: 64 tokens x 128 d. 256 thr, warp grid 2m x 4n, warp tile m32 x n32.
// A staged in smem from g_act; acc transposed through smem so ALL gmem
// traffic (x, prev, out) is float4-coalesced.
// ---------------------------------------------------------------------------
__global__ __launch_bounds__(256) void k_gemm2_mma(
    const float* __restrict__ x, const float* __restrict__ state,
    const float* __restrict__ w2,
    const float* __restrict__ mk, const float* __restrict__ mw,
    const float* __restrict__ mv, const float* __restrict__ mr,
    const float* __restrict__ mg,
    const int* __restrict__ ip,
    float* __restrict__ out, int B, int S, int D)
{
    __shared__ uint32_t As[64 * 36];   // [m][k] per-f act tile
    __shared__ uint32_t Bs[32 * 136];  // [k][d] tf32 W2 tile
    __shared__ float    Cs[32 * 132];  // acc transpose buffer (one 32-row pass)

    const int tid = threadIdx.x;
    const int wid = tid >> 5, lane = tid & 31;
    const int g = lane >> 2, t = lane & 3;
    const int warp_m = wid & 1, warp_n = wid >> 1;
    const int dbase = blockIdx.x * 128;
    const int mbase = blockIdx.y * 64;
    const int i1 = SROWS * ip[0] + 1;

    // B fill: 1024 float4 slots, 4/thread
    int br[4], bc[4];
#pragma unroll
    for (int it = 0; it < 4; it++) {
        int slot = tid + it * 256;
        br[it] = slot >> 5;
        bc[it] = (slot & 31) * 4;
    }
    // A fill: 512 float4 slots, 2/thread
    int arr[2], acg[2];
#pragma unroll
    for (int it = 0; it < 2; it++) {
        int slot = tid + it * 256;
        arr[it] = slot >> 3;
        acg[it] = (slot & 7) * 4;
    }

    for (int f = 0; f < 5; f++) {
        if (f) __syncthreads();   // prior Cs/As/Bs consumed
        // ---- stage As (g_act already tf32) ----
#pragma unroll
        for (int it = 0; it < 2; it++)
            *(uint4*)(As + arr[it] * 36 + acg[it]) =
                *(const uint4*)(g_act + (size_t)(mbase + arr[it]) * 160 + f * 32 + acg[it]);
        // ---- stage Bs (tf32 round) ----
#pragma unroll
        for (int it = 0; it < 4; it++) {
            float4 w = *(const float4*)(w2 + ((size_t)f * 32 + br[it]) * D + dbase + bc[it]);
            uint4 o;
            o.x = f2tf32(w.x); o.y = f2tf32(w.y);
            o.z = f2tf32(w.z); o.w = f2tf32(w.w);
            *(uint4*)(Bs + br[it] * 136 + bc[it]) = o;
        }
        __syncthreads();

        float acc[2][4][4];
#pragma unroll
        for (int mi = 0; mi < 2; mi++)
#pragma unroll
            for (int nt = 0; nt < 4; nt++)
#pragma unroll
                for (int j = 0; j < 4; j++) acc[mi][nt][j] = 0.f;

#pragma unroll
        for (int ks = 0; ks < 4; ks++) {
            const int k0 = ks * 8;
            uint32_t a[2][4];
#pragma unroll
            for (int mi = 0; mi < 2; mi++) {
                const int ar = warp_m * 32 + mi * 16 + g;
                a[mi][0] = As[ar * 36 + k0 + t];
                a[mi][1] = As[(ar + 8) * 36 + k0 + t];
                a[mi][2] = As[ar * 36 + k0 + t + 4];
                a[mi][3] = As[(ar + 8) * 36 + k0 + t + 4];
            }
#pragma unroll
            for (int nt = 0; nt < 4; nt++) {
                const int nc = warp_n * 32 + nt * 8 + g;
                uint32_t b0 = Bs[(k0 + t) * 136 + nc];
                uint32_t b1 = Bs[(k0 + t + 4) * 136 + nc];
#pragma unroll
                for (int mi = 0; mi < 2; mi++)
                    MMA_TF32(acc[mi][nt], a[mi][0], a[mi][1], a[mi][2], a[mi][3], b0, b1);
            }
        }

        const float* st = (f == 0) ? mk : (f == 1) ? mw : (f == 2) ? mv
                        : (f == 3) ? mr : mg;

        // ---- two passes: transpose acc through Cs, coalesced epilogue ----
#pragma unroll
        for (int pass = 0; pass < 2; pass++) {
            __syncthreads();  // Cs free (prev pass / prev f fully read)
            if (warp_m == pass) {
#pragma unroll
                for (int mi = 0; mi < 2; mi++)
#pragma unroll
                    for (int h = 0; h < 2; h++) {
                        const int row = mi * 16 + h * 8 + g;
#pragma unroll
                        for (int nt = 0; nt < 4; nt++) {
                            const int c = warp_n * 32 + nt * 8 + t * 2;
                            float2 v = make_float2(acc[mi][nt][h * 2 + 0],
                                                   acc[mi][nt][h * 2 + 1]);
                            *(float2*)(Cs + row * 132 + c) = v;
                        }
                    }
            }
            __syncthreads();
            // coalesced epilogue over rows [pass*32, pass*32+32)
#pragma unroll
            for (int it = 0; it < 4; it++) {
                int slot = tid + it * 256;
                int row = slot >> 5;
                int c = (slot & 31) * 4;
                int m = mbase + pass * 32 + row;
                int b = m / S;
                int s = m - b * S;
                const int d = dbase + c;
                float4 cv = *(const float4*)(Cs + row * 132 + c);
                float4 xv = *(const float4*)(x + (size_t)m * D + d);
                float4 pv = (s == 0)
                    ? *(const float4*)(state + ((size_t)b * SROWS + i1) * D + d)
                    : *(const float4*)(x + (size_t)(m - 1) * D + d);
                float4 stv = *(const float4*)(st + d);
                float4 o;
                o.x = fmaf(pv.x - xv.x, stv.x + cv.x, xv.x);
                o.y = fmaf(pv.y - xv.y, stv.y + cv.y, xv.y);
                o.z = fmaf(pv.z - xv.z, stv.z + cv.z, xv.z);
                o.w = fmaf(pv.w - xv.w, stv.w + cv.w, xv.w);
                *(float4*)(out + ((size_t)m * 5 + f) * D + d) = o;
            }
        }
    }
}

// ---------------------------------------------------------------------------
// Kernel C: new_state = state with row i1 <- x[:, S-1, :]
// ---------------------------------------------------------------------------
__global__ void k_state(
    const float* __restrict__ x, const float* __restrict__ state,
    const int* __restrict__ ip, float* __restrict__ outs,
    int B, int S, int D)
{
    int idx = blockIdx.x * blockDim.x + threadIdx.x;
    int n = B * SROWS * D;
    if (idx >= n) return;
    int i1 = SROWS * ip[0] + 1;
    int d = idx % D;
    int r = (idx / D) % SROWS;
    int b = idx / (D * SROWS);
    float v = (r == i1) ? x[((size_t)b * S + (S - 1)) * D + d] : state[idx];
    outs[idx] = v;
}

extern "C" void kernel_launch(void* const* d_in, const int* in_sizes, int n_in,
                              void* d_out, int out_size)
{
    const float* x     = (const float*)d_in[0];
    const float* state = (const float*)d_in[1];
    const float* tmx   = (const float*)d_in[2];
    const float* w1    = (const float*)d_in[3];
    const float* w2    = (const float*)d_in[4];
    const float* mk    = (const float*)d_in[5];
    const float* mw    = (const float*)d_in[6];
    const float* mv    = (const float*)d_in[7];
    const float* mr    = (const float*)d_in[8];
    const float* mg    = (const float*)d_in[9];
    const int*   ip    = (const int*)d_in[10];

    const int D = in_sizes[2];
    const int B = in_sizes[1] / (SROWS * D);
    const int S = in_sizes[0] / (B * D);
    const int M = B * S;

    float* out  = (float*)d_out;
    float* outs = out + (size_t)M * 5 * D;

    k_w1cv<<<(160 * D + 255) / 256, 256>>>(w1, 160 * D);
    k_gemm1_mma<<<M / 32, 256>>>(x, state, tmx, ip, B, S, D);

    dim3 g2(D / 128, M / 64);
    k_gemm2_mma<<<g2, 256>>>(x, state, w2, mk, mw, mv, mr, mg, ip, out, B, S, D);

    size_t main_elems  = (size_t)M * 5 * D;
    size_t state_elems = (size_t)B * SROWS * D;
    if ((size_t)out_size >= main_elems + state_elems) {
        int n = B * SROWS * D;
        k_state<<<(n + 255) / 256, 256>>>(x, state, ip, outs, B, S, D);
    }
}